// round 4
// baseline (speedup 1.0000x reference)
#include <cuda_runtime.h>

#define N_NODE 50000
#define N_EDGE 600000
#define D 128
#define NREL 3
#define SCAN_CHUNK 4096
#define NCHUNK ((N_NODE + SCAN_CHUNK - 1) / SCAN_CHUNK)   // 13

// ---------------- device scratch (static, no allocs) ----------------
__device__ int   g_deg   [NREL][N_NODE];
__device__ int   g_incl  [NREL][N_NODE];
__device__ int   g_offs  [NREL][N_NODE + 1];
__device__ int   g_cursor[NREL][N_NODE];
__device__ int   g_bsum  [NREL][NCHUNK];
__device__ int   g_sorted[NREL][N_EDGE];
__device__ float g_mean  [NREL][(size_t)N_NODE * D];   // 76.8 MB

// ---------------- phase 0: zero degrees ----------------
__global__ void zero_deg_kernel() {
    int i = blockIdx.x * blockDim.x + threadIdx.x;
    if (i < NREL * N_NODE) ((int*)g_deg)[i] = 0;
}

// ---------------- phase 1: count degrees (4 edges / thread, int4) --------
__global__ void count_kernel(const int* __restrict__ e0,
                             const int* __restrict__ e1,
                             const int* __restrict__ e2) {
    int i = blockIdx.x * blockDim.x + threadIdx.x;       // quad index
    int nq = N_EDGE / 4;                                  // 150000
    if (i >= NREL * nq) return;
    int r = i / nq;
    int q = i - r * nq;
    const int* ei = (r == 0) ? e0 : (r == 1) ? e1 : e2;
    int4 dst = *(const int4*)&ei[N_EDGE + q * 4];
    atomicAdd(&g_deg[r][dst.x], 1);
    atomicAdd(&g_deg[r][dst.y], 1);
    atomicAdd(&g_deg[r][dst.z], 1);
    atomicAdd(&g_deg[r][dst.w], 1);
}

// ---------------- phase 2a: per-chunk inclusive scan ----------------
__global__ void scan1_kernel() {
    int r = blockIdx.y;
    int base = blockIdx.x * SCAN_CHUNK + threadIdx.x * 4;
    int v[4];
#pragma unroll
    for (int u = 0; u < 4; u++) {
        int idx = base + u;
        v[u] = (idx < N_NODE) ? g_deg[r][idx] : 0;
    }
    int t = v[0] + v[1] + v[2] + v[3];

    __shared__ int ws[32];
    int lane = threadIdx.x & 31;
    int wid  = threadIdx.x >> 5;
    int s = t;
#pragma unroll
    for (int o = 1; o < 32; o <<= 1) {
        int n = __shfl_up_sync(0xffffffffu, s, o);
        if (lane >= o) s += n;
    }
    if (lane == 31) ws[wid] = s;
    __syncthreads();
    if (wid == 0) {
        int x = ws[lane];
#pragma unroll
        for (int o = 1; o < 32; o <<= 1) {
            int n = __shfl_up_sync(0xffffffffu, x, o);
            if (lane >= o) x += n;
        }
        ws[lane] = x;
    }
    __syncthreads();
    int excl = s - t + (wid ? ws[wid - 1] : 0);
    int run = excl;
#pragma unroll
    for (int u = 0; u < 4; u++) {
        run += v[u];
        int idx = base + u;
        if (idx < N_NODE) g_incl[r][idx] = run;
    }
    if (threadIdx.x == 0) g_bsum[r][blockIdx.x] = ws[31];
}

// ---------------- phase 2b: finalize offsets + cursors (inline chunk scan) --
__global__ void scan3_kernel() {
    int r = blockIdx.y;
    int boff = 0;
#pragma unroll
    for (int c = 0; c < NCHUNK; c++)
        if (c < blockIdx.x) boff += g_bsum[r][c];
    int base = blockIdx.x * SCAN_CHUNK + threadIdx.x * 4;
#pragma unroll
    for (int u = 0; u < 4; u++) {
        int idx = base + u;
        if (idx < N_NODE) {
            int incl = g_incl[r][idx] + boff;
            g_offs[r][idx + 1] = incl;
            g_cursor[r][idx]   = incl - g_deg[r][idx];
        }
    }
    if (blockIdx.x == 0 && threadIdx.x == 0) g_offs[r][0] = 0;
}

// ---------------- phase 3: bucket src ids by dst (4 edges / thread) -------
__global__ void bucket_kernel(const int* __restrict__ e0,
                              const int* __restrict__ e1,
                              const int* __restrict__ e2) {
    int i = blockIdx.x * blockDim.x + threadIdx.x;
    int nq = N_EDGE / 4;
    if (i >= NREL * nq) return;
    int r = i / nq;
    int q = i - r * nq;
    const int* ei = (r == 0) ? e0 : (r == 1) ? e1 : e2;
    int4 src = *(const int4*)&ei[q * 4];
    int4 dst = *(const int4*)&ei[N_EDGE + q * 4];
    g_sorted[r][atomicAdd(&g_cursor[r][dst.x], 1)] = src.x;
    g_sorted[r][atomicAdd(&g_cursor[r][dst.y], 1)] = src.y;
    g_sorted[r][atomicAdd(&g_cursor[r][dst.z], 1)] = src.z;
    g_sorted[r][atomicAdd(&g_cursor[r][dst.w], 1)] = src.w;
}

// ---------------- shared GEMM body (f32x2 packed FMA + reg prefetch) ------
#define BM 128
#define BN 128
#define BK 8
#define NB (((N_NODE) + BM - 1) / BM)    // 391 per output
#define GX_BLOCKS (2 * NB)               // 782 x@Wr blocks in the fused kernel
#define AGG_BPR 6250                     // aggregate blocks per relation
#define AGG_BLOCKS (NREL * AGG_BPR)

// out[m,d] (+=) scale * ( sum_s A_s[m,:] . W_s[d,:] (+ wb on last s) + bias )
template <bool ACCUM>
__device__ __forceinline__ void gemm_body(
    int m0, int nsrc,
    const float* const* Aarr, const float* const* Warr,
    const float* wb, const float* bias0, const float* bias1,
    float scale, float* outp)
{
    __shared__ float As[BK][BM];
    __shared__ float Bs[BK][BN];

    int tid = threadIdx.x;
    int tx  = tid & 15;        // N direction, 16 * 8 = 128
    int ty  = tid >> 4;        // M direction, 16 * 8 = 128
    int lrow = tid >> 1;       // 0..127 row for cooperative loads
    int lk4  = (tid & 1) * 4;  // 0 or 4

    unsigned long long accp[8][4];
#pragma unroll
    for (int i = 0; i < 8; i++)
#pragma unroll
        for (int j = 0; j < 4; j++) accp[i][j] = 0ull;

    int T = nsrc * (D / BK);   // tiles across all sources

    auto LOAD = [&](int t, float4& avo, float4& bvo) {
        int s  = t >> 4;               // 16 k-tiles per source
        int kk = (t & 15) * BK;
        const float* A = Aarr[s];
        const float* W = Warr[s];
        int gm = m0 + lrow;
        avo = (gm < N_NODE)
            ? *(const float4*)&A[(size_t)gm * D + kk + lk4]
            : make_float4(0.f, 0.f, 0.f, 0.f);
        float4 b = *(const float4*)&W[(size_t)lrow * D + kk + lk4];
        if (wb && s == nsrc - 1) {
            float4 w = *(const float4*)&wb[(size_t)lrow * D + kk + lk4];
            b.x += w.x; b.y += w.y; b.z += w.z; b.w += w.w;
        }
        bvo = b;
    };

    float4 av, bv;
    LOAD(0, av, bv);

    for (int t = 0; t < T; t++) {
        As[lk4 + 0][lrow] = av.x;
        As[lk4 + 1][lrow] = av.y;
        As[lk4 + 2][lrow] = av.z;
        As[lk4 + 3][lrow] = av.w;
        Bs[lk4 + 0][lrow] = bv.x;
        Bs[lk4 + 1][lrow] = bv.y;
        Bs[lk4 + 2][lrow] = bv.z;
        Bs[lk4 + 3][lrow] = bv.w;
        __syncthreads();

        float4 av2 = make_float4(0.f, 0.f, 0.f, 0.f);
        float4 bv2 = av2;
        if (t + 1 < T) LOAD(t + 1, av2, bv2);

#pragma unroll
        for (int k = 0; k < BK; k++) {
            float a_[8];
            *(float4*)&a_[0] = *(const float4*)&As[k][ty * 8];
            *(float4*)&a_[4] = *(const float4*)&As[k][ty * 8 + 4];
            ulonglong2 q0 = *(const ulonglong2*)&Bs[k][tx * 8 + 0];
            ulonglong2 q1 = *(const ulonglong2*)&Bs[k][tx * 8 + 4];
            unsigned long long bp[4] = {q0.x, q0.y, q1.x, q1.y};
#pragma unroll
            for (int i = 0; i < 8; i++) {
                unsigned long long ap;
                asm("mov.b64 %0, {%1, %1};" : "=l"(ap) : "f"(a_[i]));
#pragma unroll
                for (int j = 0; j < 4; j++)
                    asm("fma.rn.f32x2 %0, %1, %2, %0;"
                        : "+l"(accp[i][j]) : "l"(ap), "l"(bp[j]));
            }
        }
        __syncthreads();
        av = av2; bv = bv2;
    }

    // epilogue
    float bsum[8];
#pragma unroll
    for (int j = 0; j < 8; j++) {
        float b = bias0 ? bias0[tx * 8 + j] : 0.f;
        if (bias1) b += bias1[tx * 8 + j];
        bsum[j] = b;
    }
#pragma unroll
    for (int i = 0; i < 8; i++) {
        int gm = m0 + ty * 8 + i;
        if (gm < N_NODE) {
            float o[8];
#pragma unroll
            for (int j = 0; j < 4; j++) {
                float lo, hi;
                asm("mov.b64 {%0, %1}, %2;" : "=f"(lo), "=f"(hi) : "l"(accp[i][j]));
                o[2 * j]     = lo;
                o[2 * j + 1] = hi;
            }
            float4 o0, o1;
            if (ACCUM) {
                float4 p0 = *(const float4*)&outp[(size_t)gm * D + tx * 8];
                float4 p1 = *(const float4*)&outp[(size_t)gm * D + tx * 8 + 4];
                o0.x = p0.x + scale * (o[0] + bsum[0]);
                o0.y = p0.y + scale * (o[1] + bsum[1]);
                o0.z = p0.z + scale * (o[2] + bsum[2]);
                o0.w = p0.w + scale * (o[3] + bsum[3]);
                o1.x = p1.x + scale * (o[4] + bsum[4]);
                o1.y = p1.y + scale * (o[5] + bsum[5]);
                o1.z = p1.z + scale * (o[6] + bsum[6]);
                o1.w = p1.w + scale * (o[7] + bsum[7]);
            } else {
                o0.x = scale * (o[0] + bsum[0]);
                o0.y = scale * (o[1] + bsum[1]);
                o0.z = scale * (o[2] + bsum[2]);
                o0.w = scale * (o[3] + bsum[3]);
                o1.x = scale * (o[4] + bsum[4]);
                o1.y = scale * (o[5] + bsum[5]);
                o1.z = scale * (o[6] + bsum[6]);
                o1.w = scale * (o[7] + bsum[7]);
            }
            *(float4*)&outp[(size_t)gm * D + tx * 8]     = o0;
            *(float4*)&outp[(size_t)gm * D + tx * 8 + 4] = o1;
        }
    }
}

// ---------------- phase 4: FUSED  (x@Wr GEMM blocks  ||  aggregate blocks) --
// Blocks [0, GX_BLOCKS): independent x_dst @ Wr^T + bias -> writes out.
// Blocks [GX_BLOCKS, ...): 3-relation per-node mean aggregation -> g_mean.
// These are independent, so they co-schedule: GEMM is fma-bound, aggregate
// is LTS-bound; overlap hides most of the aggregation time.
__global__ void __launch_bounds__(256, 2)
fused_x_agg_kernel(const float* __restrict__ x_user,
                   const float* __restrict__ x_item,
                   const float* __restrict__ Wr_rates, const float* __restrict__ bl_rates,
                   const float* __restrict__ Wr_rev,   const float* __restrict__ bl_rev,
                   const float* __restrict__ Wr_fol,   const float* __restrict__ bl_fol,
                   float* __restrict__ out) {
    if (blockIdx.x < GX_BLOCKS) {
        // ---- GEMM_X path ----
        int out_id = (blockIdx.x >= NB) ? 1 : 0;
        int m0 = (blockIdx.x - out_id * NB) * BM;
        const float* Aarr[1];
        const float* Warr[1];
        if (out_id == 0) {
            Aarr[0] = x_user; Warr[0] = Wr_rev;
            gemm_body<false>(m0, 1, Aarr, Warr, Wr_fol,
                             bl_rev, bl_fol, 0.5f, out);
        } else {
            Aarr[0] = x_item; Warr[0] = Wr_rates;
            gemm_body<false>(m0, 1, Aarr, Warr, nullptr,
                             bl_rates, nullptr, 1.0f,
                             out + (size_t)N_NODE * D);
        }
        return;
    }
    // ---- aggregate path ----
    int a = blockIdx.x - GX_BLOCKS;
    int r = a / AGG_BPR;
    int rem = a - r * AGG_BPR;
    const float* __restrict__ xs = (r == 1) ? x_item : x_user;
    int warp = rem * 8 + (threadIdx.x >> 5);
    int lane = threadIdx.x & 31;
    if (warp >= N_NODE) return;
    int beg = g_offs[r][warp];
    int end = g_offs[r][warp + 1];

    float4 a0 = make_float4(0.f, 0.f, 0.f, 0.f);
    float4 a1 = a0, a2 = a0, a3 = a0;

    for (int e = beg; e < end; e += 32) {
        int n = end - e;
        if (n > 32) n = 32;
        int idx = (lane < n) ? g_sorted[r][e + lane] : 0;
        int j = 0;
        for (; j + 4 <= n; j += 4) {
            int s0 = __shfl_sync(0xffffffffu, idx, j + 0);
            int s1 = __shfl_sync(0xffffffffu, idx, j + 1);
            int s2 = __shfl_sync(0xffffffffu, idx, j + 2);
            int s3 = __shfl_sync(0xffffffffu, idx, j + 3);
            float4 v0 = __ldg((const float4*)(xs + (size_t)s0 * D) + lane);
            float4 v1 = __ldg((const float4*)(xs + (size_t)s1 * D) + lane);
            float4 v2 = __ldg((const float4*)(xs + (size_t)s2 * D) + lane);
            float4 v3 = __ldg((const float4*)(xs + (size_t)s3 * D) + lane);
            a0.x += v0.x; a0.y += v0.y; a0.z += v0.z; a0.w += v0.w;
            a1.x += v1.x; a1.y += v1.y; a1.z += v1.z; a1.w += v1.w;
            a2.x += v2.x; a2.y += v2.y; a2.z += v2.z; a2.w += v2.w;
            a3.x += v3.x; a3.y += v3.y; a3.z += v3.z; a3.w += v3.w;
        }
        for (; j < n; j++) {
            int s0 = __shfl_sync(0xffffffffu, idx, j);
            float4 v0 = __ldg((const float4*)(xs + (size_t)s0 * D) + lane);
            a0.x += v0.x; a0.y += v0.y; a0.z += v0.z; a0.w += v0.w;
        }
    }

    int deg = end - beg;
    float inv = (deg > 0) ? (1.0f / (float)deg) : 0.0f;
    float4 o;
    o.x = (a0.x + a1.x + a2.x + a3.x) * inv;
    o.y = (a0.y + a1.y + a2.y + a3.y) * inv;
    o.z = (a0.z + a1.z + a2.z + a3.z) * inv;
    o.w = (a0.w + a1.w + a2.w + a3.w) * inv;
    *(float4*)&g_mean[r][(size_t)warp * D + lane * 4] = o;
}

// ---------------- phase 5: mean@Wl GEMM, accumulating into out ------------
__global__ void __launch_bounds__(256, 2)
gemm_mean_kernel(const float* __restrict__ Wl_rates,
                 const float* __restrict__ Wl_rev,
                 const float* __restrict__ Wl_fol,
                 float* __restrict__ out) {
    int out_id = (blockIdx.x >= NB) ? 1 : 0;
    int m0 = (blockIdx.x - out_id * NB) * BM;
    if (out_id == 0) {
        const float* Aarr[2] = {g_mean[1], g_mean[2]};
        const float* Warr[2] = {Wl_rev, Wl_fol};
        gemm_body<true>(m0, 2, Aarr, Warr, nullptr,
                        nullptr, nullptr, 0.5f, out);
    } else {
        const float* Aarr[1] = {g_mean[0]};
        const float* Warr[1] = {Wl_rates};
        gemm_body<true>(m0, 1, Aarr, Warr, nullptr,
                        nullptr, nullptr, 1.0f,
                        out + (size_t)N_NODE * D);
    }
}

// ---------------- launcher ----------------
extern "C" void kernel_launch(void* const* d_in, const int* in_sizes, int n_in,
                              void* d_out, int out_size) {
    const float* x_user   = (const float*)d_in[0];
    const float* x_item   = (const float*)d_in[1];
    const int*   ei_rates = (const int*)d_in[2];
    const int*   ei_rev   = (const int*)d_in[3];
    const int*   ei_fol   = (const int*)d_in[4];
    const float* Wl_rates = (const float*)d_in[5];
    const float* bl_rates = (const float*)d_in[6];
    const float* Wr_rates = (const float*)d_in[7];
    const float* Wl_rev   = (const float*)d_in[8];
    const float* bl_rev   = (const float*)d_in[9];
    const float* Wr_rev   = (const float*)d_in[10];
    const float* Wl_fol   = (const float*)d_in[11];
    const float* bl_fol   = (const float*)d_in[12];
    const float* Wr_fol   = (const float*)d_in[13];

    float* outp = (float*)d_out;

    int nq = NREL * (N_EDGE / 4);
    // launch 0: zero degrees
    zero_deg_kernel<<<(NREL * N_NODE + 255) / 256, 256>>>();
    // launch 1: degree count
    count_kernel<<<(nq + 255) / 256, 256>>>(ei_rates, ei_rev, ei_fol);
    // launches 2-3: prefix sums -> CSR offsets
    dim3 sg(NCHUNK, NREL);
    scan1_kernel<<<sg, 1024>>>();
    scan3_kernel<<<sg, 1024>>>();
    // launch 4: bucket src ids by dst
    bucket_kernel<<<(nq + 255) / 256, 256>>>(ei_rates, ei_rev, ei_fol);
    // launch 5: fused x@Wr GEMM + 3-relation aggregation (overlapped)
    fused_x_agg_kernel<<<GX_BLOCKS + AGG_BLOCKS, 256>>>(
        x_user, x_item,
        Wr_rates, bl_rates, Wr_rev, bl_rev, Wr_fol, bl_fol, outp);
    // launch 6: mean@Wl GEMM accumulating into out
    gemm_mean_kernel<<<2 * NB, 256>>>(Wl_rates, Wl_rev, Wl_fol, outp);
}